// round 16
// baseline (speedup 1.0000x reference)
#include <cuda_runtime.h>
#include <cuda_bf16.h>
#include <math.h>
#include <stdint.h>

#define Nn   30000
#define NnP  30080     // padded to 235*128 for GEMM tiles
#define Ee   480000
#define ET   510000    // Ee + Nn self loops
#define Bb   48
#define HD   256       // H*D
#define NOUT 128
#define NL   10

// ---------------- device scratch (static, no allocs) ----------------
__device__ float4 d_H4[Nn * 64];       // H = gelu(prev) @ W   [N,256] fp32
__device__ float4 d_OUT4[Nn * 64];     // final layer output (pool input)
__device__ float4 d_AS4[Nn];           // alpha_src [N,4]
__device__ float4 d_AD4[Nn];           // alpha_dst [N,4]
__device__ int    d_deg[Nn];
__device__ int    d_rowptr[Nn + 1];
__device__ int    d_cursor[Nn];
__device__ int    d_colsrc[ET];
// gelu(agg out) bf16 split, GEMM A input: [NnP][256]
__device__ __nv_bfloat16 d_Gh[NnP * 256];
__device__ __nv_bfloat16 d_Gl[NnP * 256];
// W split+transposed: [9 layers][hi|lo][n=256][k=256] bf16
__device__ __nv_bfloat16 d_Wsw[9 * 2 * 256 * 256];

#define d_Hf   ((float*)d_H4)
#define d_OUTf ((float*)d_OUT4)
#define d_ASf  ((float*)d_AS4)
#define d_ADf  ((float*)d_AD4)

__device__ __forceinline__ float gelu_f(float x) {
    return 0.5f * x * (1.0f + erff(x * 0.70710678118654752f));
}
__device__ __forceinline__ uint32_t smem_u32(const void* p) {
    uint32_t a;
    asm("{ .reg .u64 t; cvta.to.shared.u64 t, %1; cvt.u32.u64 %0, t; }"
        : "=r"(a) : "l"(p));
    return a;
}
__device__ __forceinline__ void ldsm4(uint32_t* r, uint32_t addr) {
    asm volatile("ldmatrix.sync.aligned.m8n8.x4.shared.b16 {%0,%1,%2,%3}, [%4];"
                 : "=r"(r[0]), "=r"(r[1]), "=r"(r[2]), "=r"(r[3]) : "r"(addr));
}
__device__ __forceinline__ void mma16816(float* c, const uint32_t* a,
                                         const uint32_t* b) {
    asm volatile(
        "mma.sync.aligned.m16n8k16.row.col.f32.bf16.bf16.f32 "
        "{%0,%1,%2,%3}, {%4,%5,%6,%7}, {%8,%9}, {%0,%1,%2,%3};"
        : "+f"(c[0]), "+f"(c[1]), "+f"(c[2]), "+f"(c[3])
        : "r"(a[0]), "r"(a[1]), "r"(a[2]), "r"(a[3]), "r"(b[0]), "r"(b[1]));
}
__device__ __forceinline__ void cp16(uint32_t saddr, const void* gaddr) {
    asm volatile("cp.async.cg.shared.global [%0], [%1], 16;"
                 :: "r"(saddr), "l"(gaddr));
}
#define CP_COMMIT() asm volatile("cp.async.commit_group;" ::: "memory")
#define CP_WAIT1()  asm volatile("cp.async.wait_group 1;" ::: "memory")
#define CP_WAIT0()  asm volatile("cp.async.wait_group 0;" ::: "memory")

__device__ __forceinline__ float selh(float4 v, int hh) {
    return (hh == 0) ? v.x : (hh == 1) ? v.y : (hh == 2) ? v.z : v.w;
}

// ---------------- CSR build ----------------
__global__ void deg_init_kernel() {
    int i = blockIdx.x * blockDim.x + threadIdx.x;
    if (i < Nn) d_deg[i] = 1;
}
__global__ void hist_kernel(const int* __restrict__ dst) {
    int i = blockIdx.x * blockDim.x + threadIdx.x;
    if (i < Ee) atomicAdd(&d_deg[dst[i]], 1);
}
__global__ void scan_kernel() {
    __shared__ int sh[1024];
    const int t = threadIdx.x;
    const int CH = (Nn + 1023) / 1024;
    int start = t * CH, end = min(start + CH, Nn);
    int s = 0;
    for (int i = start; i < end; i++) s += d_deg[i];
    sh[t] = s;
    __syncthreads();
    for (int off = 1; off < 1024; off <<= 1) {
        int v = (t >= off) ? sh[t - off] : 0;
        __syncthreads();
        sh[t] += v;
        __syncthreads();
    }
    int run = sh[t] - s;
    for (int i = start; i < end; i++) {
        d_rowptr[i] = run; d_cursor[i] = run; run += d_deg[i];
    }
    if (t == 1023) d_rowptr[Nn] = sh[1023];
}
__global__ void scatter_kernel(const int* __restrict__ src,
                               const int* __restrict__ dst) {
    int i = blockIdx.x * blockDim.x + threadIdx.x;
    if (i >= ET) return;
    int s, d;
    if (i < Ee) { s = src[i]; d = dst[i]; }
    else        { s = d = i - Ee; }
    int pos = atomicAdd(&d_cursor[d], 1);
    d_colsrc[pos] = s;
}

// ---------------- fused prologue: sort rows | layer0+alpha | wsplit --------------
#define SORT_BLKS  3750
#define L0_BLKS    3750
#define WSP_BLKS   144    // 9 layers x 16 tiles of 64x64

__global__ void fused_pre_kernel(const float* __restrict__ Ws,
                                 const float* __restrict__ x,
                                 const float* __restrict__ W0,
                                 const float* __restrict__ a_src,
                                 const float* __restrict__ a_dst) {
    __shared__ float w[8 * 256];
    __shared__ float sa[256], sd[256];
    __shared__ float tile[64][65];
    const int b = blockIdx.x;
    const int t = threadIdx.x;

    if (b < SORT_BLKS) {
        // odd-even sort of each CSR row (warp/row) for determinism
        int wid = b * 8 + (t >> 5), lane = t & 31;
        if (wid >= Nn) return;
        int s0 = d_rowptr[wid], s1 = d_rowptr[wid + 1];
        int n = s1 - s0;
        for (int p = 0; p < n; p++) {
            for (int i = (p & 1) + 2 * lane; i + 1 < n; i += 64) {
                int a = d_colsrc[s0 + i], bb = d_colsrc[s0 + i + 1];
                if (a > bb) { d_colsrc[s0 + i] = bb; d_colsrc[s0 + i + 1] = a; }
            }
            __syncwarp();
        }
    } else if (b < SORT_BLKS + L0_BLKS) {
        // layer0: H0 = x @ W0 with fused alpha dots (warp/row)
        const int bb = b - SORT_BLKS;
        for (int i = t; i < 2048; i += 256) w[i] = W0[i];
        sa[t] = a_src[t];
        sd[t] = a_dst[t];
        __syncthreads();
        int lane = t & 31;
        int row = bb * 8 + (t >> 5);
        float xr[8];
#pragma unroll
        for (int k = 0; k < 8; k++) xr[k] = __ldg(x + row * 8 + k);
        float ps[4] = {0.f, 0.f, 0.f, 0.f}, pd[4] = {0.f, 0.f, 0.f, 0.f};
        float* op = d_Hf + (size_t)row * HD;
#pragma unroll
        for (int j = 0; j < 8; j++) {
            int col = lane + 32 * j;
            float acc = 0.f;
#pragma unroll
            for (int k = 0; k < 8; k++) acc += xr[k] * w[k * 256 + col];
            op[col] = acc;
            ps[j >> 1] += acc * sa[col];
            pd[j >> 1] += acc * sd[col];
        }
#pragma unroll
        for (int h = 0; h < 4; h++) {
#pragma unroll
            for (int off = 16; off; off >>= 1) {
                ps[h] += __shfl_xor_sync(0xffffffffu, ps[h], off);
                pd[h] += __shfl_xor_sync(0xffffffffu, pd[h], off);
            }
        }
        if (lane < 4) {
            d_ASf[row * 4 + lane] = ps[lane];
            d_ADf[row * 4 + lane] = pd[lane];
        }
    } else {
        // wsplit: smem tile transpose -> coalesced split stores
        // tile (l, kt, nt): k in [kt*64, kt*64+64), n in [nt*64, nt*64+64)
        const int bb = b - SORT_BLKS - L0_BLKS;  // [0, 144)
        const int l = bb >> 4;
        const int kt = (bb & 15) >> 2, nt = bb & 3;
        const float* Wl = Ws + (size_t)l * 65536;
        // coalesced load: consecutive t -> consecutive n
#pragma unroll
        for (int i = 0; i < 16; i++) {
            int kl = (t >> 6) * 16 + i;
            int nl = t & 63;
            tile[kl][nl] = Wl[(kt * 64 + kl) * 256 + nt * 64 + nl];
        }
        __syncthreads();
        // coalesced store: consecutive t -> consecutive k
        __nv_bfloat16* base = d_Wsw + (size_t)l * 131072;
#pragma unroll
        for (int i = 0; i < 16; i++) {
            int nl = (t >> 6) * 16 + i;
            int kl = t & 63;
            float wv = tile[kl][nl];
            __nv_bfloat16 hi = __float2bfloat16(wv);
            __nv_bfloat16 lo = __float2bfloat16(wv - __bfloat162float(hi));
            int n = nt * 64 + nl, k = kt * 64 + kl;
            base[n * 256 + k] = hi;
            base[65536 + n * 256 + k] = lo;
        }
    }
}

// ---------------- HMMA GEMM (layers 1..9): R8 config (measured best 48.8us) ------
#define SM_SA    0
#define SM_SD    1024
#define SM_BUF   2048
#define SM_BSTR  61440
#define GEMM_SMEM (2048 + 2 * 61440)

__global__ void __launch_bounds__(256, 1)
gat_gemm_kernel(const __nv_bfloat16* __restrict__ Wsw,
                const float* __restrict__ a_src,
                const float* __restrict__ a_dst) {
    extern __shared__ char smem[];
    const uint32_t sb = smem_u32(smem);
    const int tid = threadIdx.x;
    const int lane = tid & 31;
    const int wid = tid >> 5;
    const int WM = wid >> 2, WN = wid & 3;
    const int row0 = blockIdx.x * 128;

    float* sa = (float*)(smem + SM_SA);
    float* sd = (float*)(smem + SM_SD);
    sa[tid] = a_src[tid];
    sd[tid] = a_dst[tid];

    const char* Wb = (const char*)Wsw;
    const char* Ah = (const char*)d_Gh;
    const char* Al = (const char*)d_Gl;

#define PREFETCH(cc) do {                                                     \
    const int _pb = (cc) & 1;                                                 \
    const uint32_t _bs = sb + SM_BUF + _pb * SM_BSTR;                         \
    _Pragma("unroll")                                                         \
    for (int j = 0; j < 4; j++) {                                             \
        int half = j >> 1;                                                    \
        int idx = tid + (j & 1) * 256;                                        \
        int row = idx >> 2, sg = idx & 3;                                     \
        uint32_t dst = _bs + half * 10240 + row * 80 + sg * 16;               \
        const char* srcb = half ? Al : Ah;                                    \
        cp16(dst, srcb + (size_t)(row0 + row) * 512 + (cc) * 64 + sg * 16);   \
    }                                                                         \
    _Pragma("unroll")                                                         \
    for (int j = 0; j < 8; j++) {                                             \
        int half = j >> 2;                                                    \
        int idx = tid + (j & 3) * 256;                                        \
        int n = idx >> 2, sg = idx & 3;                                       \
        uint32_t dst = _bs + 20480 + half * 20480 + n * 80 + sg * 16;         \
        cp16(dst, Wb + half * 131072 + n * 512 + (cc) * 64 + sg * 16);        \
    }                                                                         \
    CP_COMMIT();                                                              \
} while (0)

    PREFETCH(0);

    float c[4][8][4];
#pragma unroll
    for (int mi = 0; mi < 4; mi++)
#pragma unroll
        for (int ni = 0; ni < 8; ni++)
#pragma unroll
            for (int q = 0; q < 4; q++) c[mi][ni][q] = 0.f;

    const uint32_t aoff = (uint32_t)((WM * 64 + (lane & 15)) * 80 +
                                     (lane >> 4) * 16);
    const uint32_t boff = (uint32_t)((WN * 64 + ((lane >> 4) & 1) * 8 +
                                      (lane & 7)) * 80 +
                                     ((lane >> 3) & 1) * 16);

    for (int cc = 0; cc < 8; cc++) {
        const int buf = cc & 1;
        __syncthreads();
        if (cc < 7) { PREFETCH(cc + 1); CP_WAIT1(); }
        else        { CP_WAIT0(); }
        __syncthreads();

        const uint32_t bs = sb + SM_BUF + buf * SM_BSTR;
        const uint32_t aH = bs, aL = bs + 10240;
        const uint32_t bH = bs + 20480, bL = bs + 40960;
#pragma unroll
        for (int s = 0; s < 2; s++) {
            const uint32_t so = (uint32_t)(s * 32);
            uint32_t ah[4][4], bh[4][4];
#pragma unroll
            for (int mi = 0; mi < 4; mi++)
                ldsm4(ah[mi], aH + aoff + mi * 1280 + so);
#pragma unroll
            for (int p = 0; p < 4; p++)
                ldsm4(bh[p], bH + boff + p * 1280 + so);
#pragma unroll
            for (int mi = 0; mi < 4; mi++)
#pragma unroll
                for (int ni = 0; ni < 8; ni++)
                    mma16816(c[mi][ni], ah[mi], &bh[ni >> 1][(ni & 1) * 2]);
            uint32_t bl[4][4];
#pragma unroll
            for (int p = 0; p < 4; p++)
                ldsm4(bl[p], bL + boff + p * 1280 + so);
#pragma unroll
            for (int mi = 0; mi < 4; mi++)
#pragma unroll
                for (int ni = 0; ni < 8; ni++)
                    mma16816(c[mi][ni], ah[mi], &bl[ni >> 1][(ni & 1) * 2]);
            uint32_t al[4][4];
#pragma unroll
            for (int mi = 0; mi < 4; mi++)
                ldsm4(al[mi], aL + aoff + mi * 1280 + so);
#pragma unroll
            for (int mi = 0; mi < 4; mi++)
#pragma unroll
                for (int ni = 0; ni < 8; ni++)
                    mma16816(c[mi][ni], al[mi], &bh[ni >> 1][(ni & 1) * 2]);
        }
    }
#undef PREFETCH

    // ---- epilogue: fused alpha dots + H writeback ----
    const int colq = WN * 64 + (lane & 3) * 2;
#pragma unroll
    for (int mi = 0; mi < 4; mi++) {
#pragma unroll
        for (int h = 0; h < 2; h++) {
            float ps = 0.f, pd = 0.f;
#pragma unroll
            for (int ni = 0; ni < 8; ni++) {
                float v0 = c[mi][ni][h * 2], v1 = c[mi][ni][h * 2 + 1];
                int col = colq + ni * 8;
                ps += v0 * sa[col] + v1 * sa[col + 1];
                pd += v0 * sd[col] + v1 * sd[col + 1];
            }
            ps += __shfl_xor_sync(0xffffffffu, ps, 1);
            ps += __shfl_xor_sync(0xffffffffu, ps, 2);
            pd += __shfl_xor_sync(0xffffffffu, pd, 1);
            pd += __shfl_xor_sync(0xffffffffu, pd, 2);
            int row = row0 + WM * 64 + mi * 16 + h * 8 + (lane >> 2);
            if ((lane & 3) == 0 && row < Nn) {
                d_ASf[row * 4 + WN] = ps;
                d_ADf[row * 4 + WN] = pd;
            }
        }
    }
#pragma unroll
    for (int mi = 0; mi < 4; mi++) {
#pragma unroll
        for (int h = 0; h < 2; h++) {
            int row = row0 + WM * 64 + mi * 16 + h * 8 + (lane >> 2);
            if (row >= Nn) continue;
            float* op = d_Hf + (size_t)row * HD;
#pragma unroll
            for (int ni = 0; ni < 8; ni++) {
                float2 v = make_float2(c[mi][ni][h * 2], c[mi][ni][h * 2 + 1]);
                *(float2*)(op + colq + ni * 8) = v;
            }
        }
    }
}

// ------ aggregation: ONE pass, post-normalized softmax, 2-deep prefetch ------
template <bool LAST>
__global__ void agg_kernel(const float* __restrict__ bias) {
    int t = blockIdx.x * blockDim.x + threadIdx.x;
    int row = t >> 5, lane = t & 31;
    if (row >= Nn) return;
    const int hh = lane >> 3;
    const int s0 = d_rowptr[row], s1 = d_rowptr[row + 1];

    const float ad = selh(__ldg(d_AD4 + row), hh);

    float z = 0.f;
    float4 acc0 = make_float4(0.f, 0.f, 0.f, 0.f);
    float4 acc1 = make_float4(0.f, 0.f, 0.f, 0.f);

    int s_cur = __ldg(d_colsrc + s0);
    float4 as_cur = __ldg(d_AS4 + s_cur);
    for (int e = s0; e < s1; e++) {
        const float4* hp = d_H4 + (size_t)s_cur * 64 + lane * 2;
        float4 v0 = hp[0], v1 = hp[1];
        int s_nxt = s_cur;
        float4 as_nxt = as_cur;
        if (e + 1 < s1) {
            s_nxt = __ldg(d_colsrc + e + 1);
            as_nxt = __ldg(d_AS4 + s_nxt);
        }
        float a = selh(as_cur, hh) + ad;
        a = a > 0.f ? a : 0.2f * a;
        float wgt = expf(a);
        z += wgt;
        acc0.x += wgt * v0.x; acc0.y += wgt * v0.y;
        acc0.z += wgt * v0.z; acc0.w += wgt * v0.w;
        acc1.x += wgt * v1.x; acc1.y += wgt * v1.y;
        acc1.z += wgt * v1.z; acc1.w += wgt * v1.w;
        s_cur = s_nxt;
        as_cur = as_nxt;
    }
    const float invz = 1.f / (z + 1e-16f);

    const float4* bp = (const float4*)(bias + lane * 8);
    float4 b0 = bp[0], b1 = bp[1];
    acc0.x = acc0.x * invz + b0.x; acc0.y = acc0.y * invz + b0.y;
    acc0.z = acc0.z * invz + b0.z; acc0.w = acc0.w * invz + b0.w;
    acc1.x = acc1.x * invz + b1.x; acc1.y = acc1.y * invz + b1.y;
    acc1.z = acc1.z * invz + b1.z; acc1.w = acc1.w * invz + b1.w;

    if (LAST) {
        float* op = d_OUTf + (size_t)row * HD + lane * 8;
        *(float4*)op = acc0;
        *(float4*)(op + 4) = acc1;
    } else {
        float g[8] = {acc0.x, acc0.y, acc0.z, acc0.w,
                      acc1.x, acc1.y, acc1.z, acc1.w};
        uint16_t hi[8], lo[8];
#pragma unroll
        for (int q = 0; q < 8; q++) {
            float gv = gelu_f(g[q]);
            __nv_bfloat16 h = __float2bfloat16(gv);
            hi[q] = __bfloat16_as_ushort(h);
            lo[q] = __bfloat16_as_ushort(
                __float2bfloat16(gv - __bfloat162float(h)));
        }
        uint4 hp, lp;
        hp.x = (uint32_t)hi[0] | ((uint32_t)hi[1] << 16);
        hp.y = (uint32_t)hi[2] | ((uint32_t)hi[3] << 16);
        hp.z = (uint32_t)hi[4] | ((uint32_t)hi[5] << 16);
        hp.w = (uint32_t)hi[6] | ((uint32_t)hi[7] << 16);
        lp.x = (uint32_t)lo[0] | ((uint32_t)lo[1] << 16);
        lp.y = (uint32_t)lo[2] | ((uint32_t)lo[3] << 16);
        lp.z = (uint32_t)lo[4] | ((uint32_t)lo[5] << 16);
        lp.w = (uint32_t)lo[6] | ((uint32_t)lo[7] << 16);
        *(uint4*)((char*)d_Gh + (size_t)row * 512 + lane * 16) = hp;
        *(uint4*)((char*)d_Gl + (size_t)row * 512 + lane * 16) = lp;
    }
}

// ---------------- fused readout: pool [min|max|mean|sum] -> gelu -> head ------
__global__ void readout_kernel(const int* __restrict__ batch,
                               const float* __restrict__ hW,
                               const float* __restrict__ hb,
                               float* __restrict__ out) {
    __shared__ float sg[1024];
    __shared__ int sbm[2];
    int b = blockIdx.x, c = threadIdx.x;
    if (c < 2) {
        int target = b + c;
        int lo = 0, hi = Nn;
        while (lo < hi) {
            int mid = (lo + hi) >> 1;
            if (batch[mid] < target) lo = mid + 1; else hi = mid;
        }
        sbm[c] = lo;
    }
    __syncthreads();
    int n0 = sbm[0], n1 = sbm[1];
    float mn = INFINITY, mx = -INFINITY, sm = 0.f;
    for (int n = n0; n < n1; n++) {
        float v = d_OUTf[(size_t)n * HD + c];
        mn = fminf(mn, v); mx = fmaxf(mx, v); sm += v;
    }
    int cnt = n1 - n0;
    if (cnt == 0) { mn = 0.f; mx = 0.f; }
    float mean = sm / fmaxf((float)cnt, 1.f);
    sg[c]       = gelu_f(mn);
    sg[256 + c] = gelu_f(mx);
    sg[512 + c] = gelu_f(mean);
    sg[768 + c] = gelu_f(sm);
    __syncthreads();
    if (c < NOUT) {
        float acc = hb[c];
        for (int k = 0; k < 1024; k++) acc += sg[k] * hW[k * NOUT + c];
        out[b * NOUT + c] = acc;
    }
}

// ---------------- launch ----------------
extern "C" void kernel_launch(void* const* d_in, const int* in_sizes, int n_in,
                              void* d_out, int out_size) {
    const float* x      = (const float*)d_in[0];
    const int*   ei     = (const int*)  d_in[1];
    const int*   batch  = (const int*)  d_in[2];
    const float* W0     = (const float*)d_in[3];
    const float* a_src0 = (const float*)d_in[4];
    const float* a_dst0 = (const float*)d_in[5];
    const float* b0     = (const float*)d_in[6];
    const float* Ws     = (const float*)d_in[7];
    const float* a_srcs = (const float*)d_in[8];
    const float* a_dsts = (const float*)d_in[9];
    const float* bs     = (const float*)d_in[10];
    const float* hW     = (const float*)d_in[11];
    const float* hb     = (const float*)d_in[12];
    float* out = (float*)d_out;

    const int* srcp = ei;
    const int* dstp = ei + Ee;

    __nv_bfloat16* pWsw = nullptr;
    cudaGetSymbolAddress((void**)&pWsw, d_Wsw);

    cudaFuncSetAttribute(gat_gemm_kernel,
                         cudaFuncAttributeMaxDynamicSharedMemorySize, GEMM_SMEM);

    deg_init_kernel<<<(Nn + 255) / 256, 256>>>();
    hist_kernel<<<(Ee + 255) / 256, 256>>>(dstp);
    scan_kernel<<<1, 1024>>>();
    scatter_kernel<<<(ET + 255) / 256, 256>>>(srcp, dstp);
    fused_pre_kernel<<<SORT_BLKS + L0_BLKS + WSP_BLKS, 256>>>(
        Ws, x, W0, a_src0, a_dst0);

    agg_kernel<false><<<(Nn * 32 + 255) / 256, 256>>>(b0);

    for (int l = 1; l < NL; l++) {
        gat_gemm_kernel<<<NnP / 128, 256, GEMM_SMEM>>>(
            pWsw + (size_t)(l - 1) * 131072,
            a_srcs + (size_t)(l - 1) * HD, a_dsts + (size_t)(l - 1) * HD);
        if (l < NL - 1)
            agg_kernel<false><<<(Nn * 32 + 255) / 256, 256>>>(
                bs + (size_t)(l - 1) * HD);
        else
            agg_kernel<true><<<(Nn * 32 + 255) / 256, 256>>>(
                bs + (size_t)(l - 1) * HD);
    }

    readout_kernel<<<Bb, 256>>>(batch, hW, hb, out);
}

// round 17
// speedup vs baseline: 1.5426x; 1.5426x over previous
#include <cuda_runtime.h>
#include <cuda_bf16.h>
#include <math.h>
#include <stdint.h>

#define Nn   30000
#define NnP  30080     // padded to 235*128 for GEMM tiles
#define Ee   480000
#define ET   510000    // Ee + Nn self loops
#define Bb   48
#define HD   256       // H*D
#define NOUT 128
#define NL   10

// ---------------- device scratch (static, no allocs) ----------------
__device__ float4 d_H4[Nn * 64];       // H = gelu(prev) @ W   [N,256] fp32
__device__ float4 d_OUT4[Nn * 64];     // final layer output (pool input)
__device__ float4 d_AS4[Nn];           // alpha_src [N,4]
__device__ float4 d_AD4[Nn];           // alpha_dst [N,4]
__device__ int    d_deg[Nn];
__device__ int    d_rowptr[Nn + 1];
__device__ int    d_cursor[Nn];
__device__ int    d_colsrc[ET];
// gelu(agg out) bf16 split, GEMM A input: [NnP][256]
__device__ __nv_bfloat16 d_Gh[NnP * 256];
__device__ __nv_bfloat16 d_Gl[NnP * 256];
// W split+transposed: [9 layers][hi|lo][n=256][k=256] bf16
__device__ __nv_bfloat16 d_Wsw[9 * 2 * 256 * 256];

#define d_Hf   ((float*)d_H4)
#define d_OUTf ((float*)d_OUT4)
#define d_ASf  ((float*)d_AS4)
#define d_ADf  ((float*)d_AD4)

__device__ __forceinline__ float gelu_f(float x) {
    return 0.5f * x * (1.0f + erff(x * 0.70710678118654752f));
}
__device__ __forceinline__ uint32_t smem_u32(const void* p) {
    uint32_t a;
    asm("{ .reg .u64 t; cvta.to.shared.u64 t, %1; cvt.u32.u64 %0, t; }"
        : "=r"(a) : "l"(p));
    return a;
}
__device__ __forceinline__ void ldsm4(uint32_t* r, uint32_t addr) {
    asm volatile("ldmatrix.sync.aligned.m8n8.x4.shared.b16 {%0,%1,%2,%3}, [%4];"
                 : "=r"(r[0]), "=r"(r[1]), "=r"(r[2]), "=r"(r[3]) : "r"(addr));
}
__device__ __forceinline__ void mma16816(float* c, const uint32_t* a,
                                         const uint32_t* b) {
    asm volatile(
        "mma.sync.aligned.m16n8k16.row.col.f32.bf16.bf16.f32 "
        "{%0,%1,%2,%3}, {%4,%5,%6,%7}, {%8,%9}, {%0,%1,%2,%3};"
        : "+f"(c[0]), "+f"(c[1]), "+f"(c[2]), "+f"(c[3])
        : "r"(a[0]), "r"(a[1]), "r"(a[2]), "r"(a[3]), "r"(b[0]), "r"(b[1]));
}
__device__ __forceinline__ void cp16(uint32_t saddr, const void* gaddr) {
    asm volatile("cp.async.cg.shared.global [%0], [%1], 16;"
                 :: "r"(saddr), "l"(gaddr));
}
#define CP_COMMIT() asm volatile("cp.async.commit_group;" ::: "memory")
#define CP_WAIT1()  asm volatile("cp.async.wait_group 1;" ::: "memory")
#define CP_WAIT0()  asm volatile("cp.async.wait_group 0;" ::: "memory")

__device__ __forceinline__ float selh(float4 v, int hh) {
    return (hh == 0) ? v.x : (hh == 1) ? v.y : (hh == 2) ? v.z : v.w;
}

// ---------------- CSR build ----------------
__global__ void deg_init_kernel() {
    int i = blockIdx.x * blockDim.x + threadIdx.x;
    if (i < Nn) d_deg[i] = 1;
}
__global__ void hist_kernel(const int* __restrict__ dst) {
    int i = blockIdx.x * blockDim.x + threadIdx.x;
    if (i < Ee) atomicAdd(&d_deg[dst[i]], 1);
}
__global__ void scan_kernel() {
    __shared__ int sh[1024];
    const int t = threadIdx.x;
    const int CH = (Nn + 1023) / 1024;
    int start = t * CH, end = min(start + CH, Nn);
    int s = 0;
    for (int i = start; i < end; i++) s += d_deg[i];
    sh[t] = s;
    __syncthreads();
    for (int off = 1; off < 1024; off <<= 1) {
        int v = (t >= off) ? sh[t - off] : 0;
        __syncthreads();
        sh[t] += v;
        __syncthreads();
    }
    int run = sh[t] - s;
    for (int i = start; i < end; i++) {
        d_rowptr[i] = run; d_cursor[i] = run; run += d_deg[i];
    }
    if (t == 1023) d_rowptr[Nn] = sh[1023];
}
__global__ void scatter_kernel(const int* __restrict__ src,
                               const int* __restrict__ dst) {
    int i = blockIdx.x * blockDim.x + threadIdx.x;
    if (i >= ET) return;
    int s, d;
    if (i < Ee) { s = src[i]; d = dst[i]; }
    else        { s = d = i - Ee; }
    int pos = atomicAdd(&d_cursor[d], 1);
    d_colsrc[pos] = s;
}

// ---------------- fused prologue: sort rows | layer0+alpha | wsplit --------------
#define SORT_BLKS  3750
#define L0_BLKS    3750
#define WSP_BLKS   2304

__global__ void fused_pre_kernel(const float* __restrict__ Ws,
                                 const float* __restrict__ x,
                                 const float* __restrict__ W0,
                                 const float* __restrict__ a_src,
                                 const float* __restrict__ a_dst) {
    __shared__ float w[8 * 256];
    __shared__ float sa[256], sd[256];
    const int b = blockIdx.x;
    const int t = threadIdx.x;

    if (b < SORT_BLKS) {
        int wid = b * 8 + (t >> 5), lane = t & 31;
        if (wid >= Nn) return;
        int s0 = d_rowptr[wid], s1 = d_rowptr[wid + 1];
        int n = s1 - s0;
        for (int p = 0; p < n; p++) {
            for (int i = (p & 1) + 2 * lane; i + 1 < n; i += 64) {
                int a = d_colsrc[s0 + i], bb = d_colsrc[s0 + i + 1];
                if (a > bb) { d_colsrc[s0 + i] = bb; d_colsrc[s0 + i + 1] = a; }
            }
            __syncwarp();
        }
    } else if (b < SORT_BLKS + L0_BLKS) {
        const int bb = b - SORT_BLKS;
        for (int i = t; i < 2048; i += 256) w[i] = W0[i];
        sa[t] = a_src[t];
        sd[t] = a_dst[t];
        __syncthreads();
        int lane = t & 31;
        int row = bb * 8 + (t >> 5);
        float xr[8];
#pragma unroll
        for (int k = 0; k < 8; k++) xr[k] = __ldg(x + row * 8 + k);
        float ps[4] = {0.f, 0.f, 0.f, 0.f}, pd[4] = {0.f, 0.f, 0.f, 0.f};
        float* op = d_Hf + (size_t)row * HD;
#pragma unroll
        for (int j = 0; j < 8; j++) {
            int col = lane + 32 * j;
            float acc = 0.f;
#pragma unroll
            for (int k = 0; k < 8; k++) acc += xr[k] * w[k * 256 + col];
            op[col] = acc;
            ps[j >> 1] += acc * sa[col];
            pd[j >> 1] += acc * sd[col];
        }
#pragma unroll
        for (int h = 0; h < 4; h++) {
#pragma unroll
            for (int off = 16; off; off >>= 1) {
                ps[h] += __shfl_xor_sync(0xffffffffu, ps[h], off);
                pd[h] += __shfl_xor_sync(0xffffffffu, pd[h], off);
            }
        }
        if (lane < 4) {
            d_ASf[row * 4 + lane] = ps[lane];
            d_ADf[row * 4 + lane] = pd[lane];
        }
    } else {
        int idx = (b - SORT_BLKS - L0_BLKS) * 256 + t;
        if (idx >= 9 * 65536) return;
        int l = idx >> 16;
        int rem = idx & 65535;
        int k = rem >> 8, n = rem & 255;
        float wv = Ws[idx];
        __nv_bfloat16 hi = __float2bfloat16(wv);
        __nv_bfloat16 lo = __float2bfloat16(wv - __bfloat162float(hi));
        __nv_bfloat16* base = d_Wsw + (size_t)l * 131072;
        base[n * 256 + k] = hi;
        base[65536 + n * 256 + k] = lo;
    }
}

// ---------------- HMMA GEMM (layers 1..9): R8 config (measured best 48.8us) ------
#define SM_SA    0
#define SM_SD    1024
#define SM_BUF   2048
#define SM_BSTR  61440
#define GEMM_SMEM (2048 + 2 * 61440)

__global__ void __launch_bounds__(256, 1)
gat_gemm_kernel(const __nv_bfloat16* __restrict__ Wsw,
                const float* __restrict__ a_src,
                const float* __restrict__ a_dst) {
    extern __shared__ char smem[];
    const uint32_t sb = smem_u32(smem);
    const int tid = threadIdx.x;
    const int lane = tid & 31;
    const int wid = tid >> 5;
    const int WM = wid >> 2, WN = wid & 3;
    const int row0 = blockIdx.x * 128;

    float* sa = (float*)(smem + SM_SA);
    float* sd = (float*)(smem + SM_SD);
    sa[tid] = a_src[tid];
    sd[tid] = a_dst[tid];

    const char* Wb = (const char*)Wsw;
    const char* Ah = (const char*)d_Gh;
    const char* Al = (const char*)d_Gl;

#define PREFETCH(cc) do {                                                     \
    const int _pb = (cc) & 1;                                                 \
    const uint32_t _bs = sb + SM_BUF + _pb * SM_BSTR;                         \
    _Pragma("unroll")                                                         \
    for (int j = 0; j < 4; j++) {                                             \
        int half = j >> 1;                                                    \
        int idx = tid + (j & 1) * 256;                                        \
        int row = idx >> 2, sg = idx & 3;                                     \
        uint32_t dst = _bs + half * 10240 + row * 80 + sg * 16;               \
        const char* srcb = half ? Al : Ah;                                    \
        cp16(dst, srcb + (size_t)(row0 + row) * 512 + (cc) * 64 + sg * 16);   \
    }                                                                         \
    _Pragma("unroll")                                                         \
    for (int j = 0; j < 8; j++) {                                             \
        int half = j >> 2;                                                    \
        int idx = tid + (j & 3) * 256;                                        \
        int n = idx >> 2, sg = idx & 3;                                       \
        uint32_t dst = _bs + 20480 + half * 20480 + n * 80 + sg * 16;         \
        cp16(dst, Wb + half * 131072 + n * 512 + (cc) * 64 + sg * 16);        \
    }                                                                         \
    CP_COMMIT();                                                              \
} while (0)

    PREFETCH(0);

    float c[4][8][4];
#pragma unroll
    for (int mi = 0; mi < 4; mi++)
#pragma unroll
        for (int ni = 0; ni < 8; ni++)
#pragma unroll
            for (int q = 0; q < 4; q++) c[mi][ni][q] = 0.f;

    const uint32_t aoff = (uint32_t)((WM * 64 + (lane & 15)) * 80 +
                                     (lane >> 4) * 16);
    const uint32_t boff = (uint32_t)((WN * 64 + ((lane >> 4) & 1) * 8 +
                                      (lane & 7)) * 80 +
                                     ((lane >> 3) & 1) * 16);

    for (int cc = 0; cc < 8; cc++) {
        const int buf = cc & 1;
        __syncthreads();
        if (cc < 7) { PREFETCH(cc + 1); CP_WAIT1(); }
        else        { CP_WAIT0(); }
        __syncthreads();

        const uint32_t bs = sb + SM_BUF + buf * SM_BSTR;
        const uint32_t aH = bs, aL = bs + 10240;
        const uint32_t bH = bs + 20480, bL = bs + 40960;
#pragma unroll
        for (int s = 0; s < 2; s++) {
            const uint32_t so = (uint32_t)(s * 32);
            uint32_t ah[4][4], bh[4][4];
#pragma unroll
            for (int mi = 0; mi < 4; mi++)
                ldsm4(ah[mi], aH + aoff + mi * 1280 + so);
#pragma unroll
            for (int p = 0; p < 4; p++)
                ldsm4(bh[p], bH + boff + p * 1280 + so);
#pragma unroll
            for (int mi = 0; mi < 4; mi++)
#pragma unroll
                for (int ni = 0; ni < 8; ni++)
                    mma16816(c[mi][ni], ah[mi], &bh[ni >> 1][(ni & 1) * 2]);
            uint32_t bl[4][4];
#pragma unroll
            for (int p = 0; p < 4; p++)
                ldsm4(bl[p], bL + boff + p * 1280 + so);
#pragma unroll
            for (int mi = 0; mi < 4; mi++)
#pragma unroll
                for (int ni = 0; ni < 8; ni++)
                    mma16816(c[mi][ni], ah[mi], &bl[ni >> 1][(ni & 1) * 2]);
            uint32_t al[4][4];
#pragma unroll
            for (int mi = 0; mi < 4; mi++)
                ldsm4(al[mi], aL + aoff + mi * 1280 + so);
#pragma unroll
            for (int mi = 0; mi < 4; mi++)
#pragma unroll
                for (int ni = 0; ni < 8; ni++)
                    mma16816(c[mi][ni], al[mi], &bh[ni >> 1][(ni & 1) * 2]);
        }
    }
#undef PREFETCH

    // ---- epilogue: fused alpha dots + H writeback ----
    const int colq = WN * 64 + (lane & 3) * 2;
#pragma unroll
    for (int mi = 0; mi < 4; mi++) {
#pragma unroll
        for (int h = 0; h < 2; h++) {
            float ps = 0.f, pd = 0.f;
#pragma unroll
            for (int ni = 0; ni < 8; ni++) {
                float v0 = c[mi][ni][h * 2], v1 = c[mi][ni][h * 2 + 1];
                int col = colq + ni * 8;
                ps += v0 * sa[col] + v1 * sa[col + 1];
                pd += v0 * sd[col] + v1 * sd[col + 1];
            }
            ps += __shfl_xor_sync(0xffffffffu, ps, 1);
            ps += __shfl_xor_sync(0xffffffffu, ps, 2);
            pd += __shfl_xor_sync(0xffffffffu, pd, 1);
            pd += __shfl_xor_sync(0xffffffffu, pd, 2);
            int row = row0 + WM * 64 + mi * 16 + h * 8 + (lane >> 2);
            if ((lane & 3) == 0 && row < Nn) {
                d_ASf[row * 4 + WN] = ps;
                d_ADf[row * 4 + WN] = pd;
            }
        }
    }
#pragma unroll
    for (int mi = 0; mi < 4; mi++) {
#pragma unroll
        for (int h = 0; h < 2; h++) {
            int row = row0 + WM * 64 + mi * 16 + h * 8 + (lane >> 2);
            if (row >= Nn) continue;
            float* op = d_Hf + (size_t)row * HD;
#pragma unroll
            for (int ni = 0; ni < 8; ni++) {
                float2 v = make_float2(c[mi][ni][h * 2], c[mi][ni][h * 2 + 1]);
                *(float2*)(op + colq + ni * 8) = v;
            }
        }
    }
}

// ------ aggregation: ONE pass, post-normalized softmax, 2-deep prefetch ------
template <bool LAST>
__global__ void agg_kernel(const float* __restrict__ bias) {
    int t = blockIdx.x * blockDim.x + threadIdx.x;
    int row = t >> 5, lane = t & 31;
    if (row >= Nn) return;
    const int hh = lane >> 3;
    const int s0 = d_rowptr[row], s1 = d_rowptr[row + 1];

    const float ad = selh(__ldg(d_AD4 + row), hh);

    float z = 0.f;
    float4 acc0 = make_float4(0.f, 0.f, 0.f, 0.f);
    float4 acc1 = make_float4(0.f, 0.f, 0.f, 0.f);

    int s_cur = __ldg(d_colsrc + s0);
    float4 as_cur = __ldg(d_AS4 + s_cur);
    for (int e = s0; e < s1; e++) {
        const float4* hp = d_H4 + (size_t)s_cur * 64 + lane * 2;
        float4 v0 = hp[0], v1 = hp[1];
        int s_nxt = s_cur;
        float4 as_nxt = as_cur;
        if (e + 1 < s1) {
            s_nxt = __ldg(d_colsrc + e + 1);
            as_nxt = __ldg(d_AS4 + s_nxt);
        }
        float a = selh(as_cur, hh) + ad;
        a = a > 0.f ? a : 0.2f * a;
        float wgt = expf(a);
        z += wgt;
        acc0.x += wgt * v0.x; acc0.y += wgt * v0.y;
        acc0.z += wgt * v0.z; acc0.w += wgt * v0.w;
        acc1.x += wgt * v1.x; acc1.y += wgt * v1.y;
        acc1.z += wgt * v1.z; acc1.w += wgt * v1.w;
        s_cur = s_nxt;
        as_cur = as_nxt;
    }
    const float invz = 1.f / (z + 1e-16f);

    const float4* bp = (const float4*)(bias + lane * 8);
    float4 b0 = bp[0], b1 = bp[1];
    acc0.x = acc0.x * invz + b0.x; acc0.y = acc0.y * invz + b0.y;
    acc0.z = acc0.z * invz + b0.z; acc0.w = acc0.w * invz + b0.w;
    acc1.x = acc1.x * invz + b1.x; acc1.y = acc1.y * invz + b1.y;
    acc1.z = acc1.z * invz + b1.z; acc1.w = acc1.w * invz + b1.w;

    if (LAST) {
        float* op = d_OUTf + (size_t)row * HD + lane * 8;
        *(float4*)op = acc0;
        *(float4*)(op + 4) = acc1;
    } else {
        float g[8] = {acc0.x, acc0.y, acc0.z, acc0.w,
                      acc1.x, acc1.y, acc1.z, acc1.w};
        uint16_t hi[8], lo[8];
#pragma unroll
        for (int q = 0; q < 8; q++) {
            float gv = gelu_f(g[q]);
            __nv_bfloat16 h = __float2bfloat16(gv);
            hi[q] = __bfloat16_as_ushort(h);
            lo[q] = __bfloat16_as_ushort(
                __float2bfloat16(gv - __bfloat162float(h)));
        }
        uint4 hp, lp;
        hp.x = (uint32_t)hi[0] | ((uint32_t)hi[1] << 16);
        hp.y = (uint32_t)hi[2] | ((uint32_t)hi[3] << 16);
        hp.z = (uint32_t)hi[4] | ((uint32_t)hi[5] << 16);
        hp.w = (uint32_t)hi[6] | ((uint32_t)hi[7] << 16);
        lp.x = (uint32_t)lo[0] | ((uint32_t)lo[1] << 16);
        lp.y = (uint32_t)lo[2] | ((uint32_t)lo[3] << 16);
        lp.z = (uint32_t)lo[4] | ((uint32_t)lo[5] << 16);
        lp.w = (uint32_t)lo[6] | ((uint32_t)lo[7] << 16);
        *(uint4*)((char*)d_Gh + (size_t)row * 512 + lane * 16) = hp;
        *(uint4*)((char*)d_Gl + (size_t)row * 512 + lane * 16) = lp;
    }
}

// ---------------- fused readout: pool [min|max|mean|sum] -> gelu -> head ------
__global__ void readout_kernel(const int* __restrict__ batch,
                               const float* __restrict__ hW,
                               const float* __restrict__ hb,
                               float* __restrict__ out) {
    __shared__ float sg[1024];
    __shared__ int sbm[2];
    int b = blockIdx.x, c = threadIdx.x;
    if (c < 2) {
        int target = b + c;
        int lo = 0, hi = Nn;
        while (lo < hi) {
            int mid = (lo + hi) >> 1;
            if (batch[mid] < target) lo = mid + 1; else hi = mid;
        }
        sbm[c] = lo;
    }
    __syncthreads();
    int n0 = sbm[0], n1 = sbm[1];
    float mn = INFINITY, mx = -INFINITY, sm = 0.f;
    for (int n = n0; n < n1; n++) {
        float v = d_OUTf[(size_t)n * HD + c];
        mn = fminf(mn, v); mx = fmaxf(mx, v); sm += v;
    }
    int cnt = n1 - n0;
    if (cnt == 0) { mn = 0.f; mx = 0.f; }
    float mean = sm / fmaxf((float)cnt, 1.f);
    sg[c]       = gelu_f(mn);
    sg[256 + c] = gelu_f(mx);
    sg[512 + c] = gelu_f(mean);
    sg[768 + c] = gelu_f(sm);
    __syncthreads();
    if (c < NOUT) {
        float acc = hb[c];
        for (int k = 0; k < 1024; k++) acc += sg[k] * hW[k * NOUT + c];
        out[b * NOUT + c] = acc;
    }
}

// ---------------- launch ----------------
extern "C" void kernel_launch(void* const* d_in, const int* in_sizes, int n_in,
                              void* d_out, int out_size) {
    const float* x      = (const float*)d_in[0];
    const int*   ei     = (const int*)  d_in[1];
    const int*   batch  = (const int*)  d_in[2];
    const float* W0     = (const float*)d_in[3];
    const float* a_src0 = (const float*)d_in[4];
    const float* a_dst0 = (const float*)d_in[5];
    const float* b0     = (const float*)d_in[6];
    const float* Ws     = (const float*)d_in[7];
    const float* a_srcs = (const float*)d_in[8];
    const float* a_dsts = (const float*)d_in[9];
    const float* bs     = (const float*)d_in[10];
    const float* hW     = (const float*)d_in[11];
    const float* hb     = (const float*)d_in[12];
    float* out = (float*)d_out;

    const int* srcp = ei;
    const int* dstp = ei + Ee;

    __nv_bfloat16* pWsw = nullptr;
    cudaGetSymbolAddress((void**)&pWsw, d_Wsw);

    cudaFuncSetAttribute(gat_gemm_kernel,
                         cudaFuncAttributeMaxDynamicSharedMemorySize, GEMM_SMEM);

    deg_init_kernel<<<(Nn + 255) / 256, 256>>>();
    hist_kernel<<<(Ee + 255) / 256, 256>>>(dstp);
    scan_kernel<<<1, 1024>>>();
    scatter_kernel<<<(ET + 255) / 256, 256>>>(srcp, dstp);
    fused_pre_kernel<<<SORT_BLKS + L0_BLKS + WSP_BLKS, 256>>>(
        Ws, x, W0, a_src0, a_dst0);

    agg_kernel<false><<<(Nn * 32 + 255) / 256, 256>>>(b0);

    for (int l = 1; l < NL; l++) {
        gat_gemm_kernel<<<NnP / 128, 256, GEMM_SMEM>>>(
            pWsw + (size_t)(l - 1) * 131072,
            a_srcs + (size_t)(l - 1) * HD, a_dsts + (size_t)(l - 1) * HD);
        if (l < NL - 1)
            agg_kernel<false><<<(Nn * 32 + 255) / 256, 256>>>(
                bs + (size_t)(l - 1) * HD);
        else
            agg_kernel<true><<<(Nn * 32 + 255) / 256, 256>>>(
                bs + (size_t)(l - 1) * HD);
    }

    readout_kernel<<<Bb, 256>>>(batch, hW, hb, out);
}